// round 2
// baseline (speedup 1.0000x reference)
#include <cuda_runtime.h>

#define H      1024
#define NSTATE 32
#define LLEN   2048
#define CHUNK  16
#define TPB    (LLEN / CHUNK)   // 128 threads, thread t owns l in [16t, 16t+16)

__global__ void __launch_bounds__(TPB) s4d_kernel(
    const float* __restrict__ log_dt,
    const float* __restrict__ log_A_real,
    const float* __restrict__ A_imag,
    const float* __restrict__ B_re, const float* __restrict__ B_im,
    const float* __restrict__ C_re, const float* __restrict__ C_im,
    float* __restrict__ out)
{
    __shared__ float2 sa[NSTATE];        // A_bar
    __shared__ float2 sw[NSTATE];        // C * B_bar
    __shared__ float2 spw[7][NSTATE];    // A_bar^(16 * 2^k), k=0..6

    const int h   = blockIdx.x;
    const int tid = threadIdx.x;

    // ---- per-(h,n) setup in fp64 (one warp) ----
    if (tid < NSTATE) {
        const int n   = tid;
        const int idx = h * NSTATE + n;
        double dt = exp((double)log_dt[h]);
        double Ar = -exp((double)log_A_real[idx]);
        double Ai = (double)A_imag[idx];
        double dr = dt * Ar, di = dt * Ai;
        double er  = exp(dr);
        double abr = er * cos(di), abi = er * sin(di);      // A_bar = exp(dt*A)
        // B_bar = (A_bar - 1)/A * B
        double xr = abr - 1.0, xi = abi;
        double den = Ar * Ar + Ai * Ai;
        double qr = (xr * Ar + xi * Ai) / den;
        double qi = (xi * Ar - xr * Ai) / den;
        double Br = (double)B_re[idx], Bi = (double)B_im[idx];
        double bbr = qr * Br - qi * Bi, bbi = qr * Bi + qi * Br;
        // w = C * B_bar
        double Cr = (double)C_re[idx], Ci = (double)C_im[idx];
        double wr = Cr * bbr - Ci * bbi, wi = Cr * bbi + Ci * bbr;

        sw[n] = make_float2((float)wr, (float)wi);
        sa[n] = make_float2((float)abr, (float)abi);

        // A_bar^16 via 4 fp64 squarings, then 7 doubling powers
        double pr = abr, pi = abi;
        #pragma unroll
        for (int k = 0; k < 4; k++) {
            double t = pr * pr - pi * pi;
            pi = 2.0 * pr * pi;
            pr = t;
        }
        #pragma unroll
        for (int k = 0; k < 7; k++) {
            spw[k][n] = make_float2((float)pr, (float)pi);
            double t = pr * pr - pi * pi;
            pi = 2.0 * pr * pi;
            pr = t;
        }
    }
    __syncthreads();

    // ---- main: K[h, 16*tid + j] = Re( sum_n w_n * A_bar_n^(16*tid + j) ) ----
    float acc[CHUNK];
    #pragma unroll
    for (int j = 0; j < CHUNK; j++) acc[j] = 0.0f;

    #pragma unroll 2
    for (int n = 0; n < NSTATE; n++) {
        const float2 a = sa[n];
        float2 s = sw[n];                       // s = w
        // s *= A_bar^(16*tid)  (binary exponentiation, predicated cmuls)
        #pragma unroll
        for (int k = 0; k < 7; k++) {
            if (tid & (1 << k)) {
                const float2 p = spw[k][n];
                float nr = fmaf(s.x, p.x, -s.y * p.y);
                float ni = fmaf(s.x, p.y,  s.y * p.x);
                s.x = nr; s.y = ni;
            }
        }
        // 16-step geometric recurrence
        #pragma unroll
        for (int j = 0; j < CHUNK; j++) {
            acc[j] += s.x;
            float nr = fmaf(s.x, a.x, -s.y * a.y);
            float ni = fmaf(s.x, a.y,  s.y * a.x);
            s.x = nr; s.y = ni;
        }
    }

    // vectorized store: 16 consecutive floats per thread = 4x STG.128
    float4* o = reinterpret_cast<float4*>(out + (size_t)h * LLEN + tid * CHUNK);
    #pragma unroll
    for (int j = 0; j < 4; j++)
        o[j] = make_float4(acc[4*j], acc[4*j+1], acc[4*j+2], acc[4*j+3]);
}

extern "C" void kernel_launch(void* const* d_in, const int* in_sizes, int n_in,
                              void* d_out, int out_size) {
    s4d_kernel<<<H, TPB>>>(
        (const float*)d_in[0],   // log_dt
        (const float*)d_in[1],   // log_A_real
        (const float*)d_in[2],   // A_imag
        (const float*)d_in[3],   // B_re
        (const float*)d_in[4],   // B_im
        (const float*)d_in[5],   // C_re
        (const float*)d_in[6],   // C_im
        (float*)d_out);
}